// round 14
// baseline (speedup 1.0000x reference)
#include <cuda_runtime.h>
#include <math.h>

// Fixed shapes: B x 3 x 512 x 960
#define IMG_H 512
#define IMG_W 960
#define NCH 3

#define TW 64          // output cols per tile (thread owns 2 adjacent cols)
#define TH 8           // output rows per tile (one warp per row)
#define PITCH 68       // float2 units per smem row (16B-aligned rows)
#define NTHR 256

#define ALPHA 0.85f
#define C1 (0.01f * 0.01f)
#define C2 (0.03f * 0.03f)
#define EPS2 (0.001f * 0.001f)

__device__ double g_accP = 0.0, g_accL = 0.0, g_accD = 0.0;
__device__ unsigned int g_ticket = 0;

__device__ __forceinline__ float fast_sqrt_pos(float x) {
    return x * rsqrtf(x);   // x >= EPS2 > 0
}

typedef unsigned long long ull;
__device__ __forceinline__ ull f2u(float2 v) {
    ull u; asm("mov.b64 %0, {%1, %2};" : "=l"(u) : "f"(v.x), "f"(v.y)); return u;
}
__device__ __forceinline__ float2 u2f(ull u) {
    float2 v; asm("mov.b64 {%0, %1}, %2;" : "=f"(v.x), "=f"(v.y) : "l"(u)); return v;
}
__device__ __forceinline__ ull x2add(ull a, ull b) {
    ull r; asm("add.rn.f32x2 %0, %1, %2;" : "=l"(r) : "l"(a), "l"(b)); return r;
}
__device__ __forceinline__ ull x2mul(ull a, ull b) {
    ull r; asm("mul.rn.f32x2 %0, %1, %2;" : "=l"(r) : "l"(a), "l"(b)); return r;
}
__device__ __forceinline__ ull x2fma(ull a, ull b, ull c) {
    ull r; asm("fma.rn.f32x2 %0, %1, %2, %3;" : "=l"(r) : "l"(a), "l"(b), "l"(c)); return r;
}

__global__ __launch_bounds__(NTHR, 7) void stereo_loss_kernel(
    const float* __restrict__ left,
    const float* __restrict__ right,
    const float* __restrict__ d_left,
    const float* __restrict__ d_right,
    const float* __restrict__ nonocc,
    float* __restrict__ out,
    int nblocks, int total_px)
{
    const int W = IMG_W, H = IMG_H;
    // sAB[c][i][j]: (left, warped right); j=0 is col w0-1, 16B aligned.
    __shared__ __align__(16) float2 sAB[NCH][TH + 2][PITCH];
    __shared__ float sD[TH + 2][PITCH];

    const int w0 = blockIdx.x * TW;
    const int h0 = blockIdx.y * TH;
    const int b  = blockIdx.z;

    const size_t planeHW = (size_t)H * W;
    const float* Lb  = left    + (size_t)b * NCH * planeHW;
    const float* Rb  = right   + (size_t)b * NCH * planeHW;
    const float* Db  = d_left  + (size_t)b * planeHW;
    const float* DRb = d_right + (size_t)b * planeHW;
    const float* Nb  = nonocc  + (size_t)b * planeHW;

    // ---- halo fill: (TH+2) x (TW+2) region; zero outside image ----
    for (int idx = threadIdx.x; idx < (TH + 2) * (TW + 2); idx += NTHR) {
        int i = idx / (TW + 2);
        int j = idx - i * (TW + 2);
        int gh = h0 - 1 + i;
        int gw = w0 - 1 + j;
        if (gh >= 0 && gh < H && gw >= 0 && gw < W) {
            float d = Db[(size_t)gh * W + gw];
            sD[i][j] = d;
            float x  = (float)gw - d;
            float x0 = floorf(x);
            float wx = x - x0;
            int   xi = (int)x0;
            int x0i = min(max(xi, 0), W - 1);
            int x1i = min(max(xi + 1, 0), W - 1);
            const float* rrow = Rb + (size_t)gh * W;
            const float* lrow = Lb + (size_t)gh * W;
            #pragma unroll
            for (int c = 0; c < NCH; c++) {
                float v0 = rrow[(size_t)c * planeHW + x0i];
                float v1 = rrow[(size_t)c * planeHW + x1i];
                float bb = (1.0f - wx) * v0 + wx * v1;
                float aa = lrow[(size_t)c * planeHW + gw];
                sAB[c][i][j] = make_float2(aa, bb);
            }
        } else {
            sD[i][j] = 0.0f;
            #pragma unroll
            for (int c = 0; c < NCH; c++) sAB[c][i][j] = make_float2(0.0f, 0.0f);
        }
    }
    __syncthreads();

    const int u  = threadIdx.x & 31;     // lane: column pair index
    const int r  = threadIdx.x >> 5;     // warp id = output row within tile
    const int gh = h0 + r;

    // ---- validity / weight for the two columns (cols 2u, 2u+1) ----
    const int c0g = w0 + 2 * u;
    float wv[2], invk[2], dls[2];
    {
        const float2 nb = *reinterpret_cast<const float2*>(Nb + (size_t)gh * W + c0g);
        // NOTE: odd float offset -> two scalar LDS.32 (LDS.64 would be misaligned)
        dls[0] = sD[r + 1][2 * u + 1];
        dls[1] = sD[r + 1][2 * u + 2];
        const bool rowsIn = (gh > 0) & (gh < H - 1);
        #pragma unroll
        for (int k = 0; k < 2; k++) {
            const int g = c0g + k;
            float dl = dls[k];
            float x  = (float)g - dl;
            float gx = 2.0f * x / (float)(W - 1) - 1.0f;
            float vb = (gx >= -1.0f && gx <= 1.0f) ? 1.0f : 0.0f;
            wv[k] = vb * (k ? nb.y : nb.x);
            const bool colsIn = (g > 0) & (g < W - 1);
            invk[k] = rowsIn ? (colsIn ? (1.0f / 9.0f) : (1.0f / 6.0f))
                             : (colsIn ? (1.0f / 6.0f) : (1.0f / 4.0f));
        }
    }
    float accD = wv[0] + wv[1];

    const ull UNEG1 = f2u(make_float2(-1.0f, -1.0f));
    const ull UTWO  = f2u(make_float2(2.0f, 2.0f));
    const ull UC1   = f2u(make_float2(C1, C1));
    const ull UC2   = f2u(make_float2(C2, C2));
    const ull UEPSD = f2u(make_float2(1e-12f, 1e-12f));
    const ull UEPS2 = f2u(make_float2(EPS2, EPS2));
    const ull uinv  = f2u(make_float2(invk[0], invk[1]));

    float ssum[2]  = {0.f, 0.f};
    float l1sum[2] = {0.f, 0.f};

    #pragma unroll
    for (int c = 0; c < NCH; c++) {
        ull acc01_0 = 0ull, acc01_1 = 0ull;   // (sumA, sumB) per col
        ull acc23_0 = 0ull, acc23_1 = 0ull;   // (sumA2, sumB2) per col
        float acc4_0 = 0.f, acc4_1 = 0.f;     // sumAB per col
        ull cab0 = 0ull, cab1 = 0ull;         // center (A,B) per col
        #pragma unroll
        for (int q = 0; q < 3; q++) {
            const float4* rowp = reinterpret_cast<const float4*>(&sAB[c][r + q][0]);
            float4 v1 = rowp[u];       // cols 2u-1, 2u
            float4 v2 = rowp[u + 1];   // cols 2u+1, 2u+2
            ull u0 = f2u(make_float2(v1.x, v1.y));
            ull u1 = f2u(make_float2(v1.z, v1.w));
            ull u2 = f2u(make_float2(v2.x, v2.y));
            ull u3 = f2u(make_float2(v2.z, v2.w));
            // shared middle partials
            ull m01 = x2add(u1, u2);
            ull msq = x2fma(u1, u1, x2mul(u2, u2));
            float xm = fmaf(v1.z, v1.w, v2.x * v2.y);
            acc01_0 = x2add(acc01_0, x2add(u0, m01));
            acc01_1 = x2add(acc01_1, x2add(m01, u3));
            acc23_0 = x2add(acc23_0, x2fma(u0, u0, msq));
            acc23_1 = x2add(acc23_1, x2fma(u3, u3, msq));
            acc4_0 += fmaf(v1.x, v1.y, xm);
            acc4_1 += fmaf(v2.z, v2.w, xm);
            if (q == 1) { cab0 = u1; cab1 = u2; }
        }

        // ---- SSIM consume, packed across the two columns ----
        float2 a0 = u2f(acc01_0), a1 = u2f(acc01_1);
        float2 b0 = u2f(acc23_0), b1 = u2f(acc23_1);
        ull sx  = f2u(make_float2(a0.x, a1.x));
        ull sy  = f2u(make_float2(a0.y, a1.y));
        ull sxx = f2u(make_float2(b0.x, b1.x));
        ull syy = f2u(make_float2(b0.y, b1.y));
        ull sxy = f2u(make_float2(acc4_0, acc4_1));

        ull mux  = x2mul(sx, uinv);
        ull muy  = x2mul(sy, uinv);
        ull nmux = x2mul(mux, UNEG1);
        ull nmuy = x2mul(muy, UNEG1);
        ull sigx  = x2fma(nmux, mux, x2mul(sxx, uinv));
        ull sigy  = x2fma(nmuy, muy, x2mul(syy, uinv));
        ull sigxy = x2fma(nmux, muy, x2mul(sxy, uinv));
        ull mm   = x2mul(mux, muy);
        ull num  = x2mul(x2fma(mm, UTWO, UC1), x2fma(sigxy, UTWO, UC2));
        ull den1 = x2fma(mux, mux, x2fma(muy, muy, UC1));
        ull den2 = x2add(x2add(sigx, sigy), UC2);
        ull den  = x2fma(den1, den2, UEPSD);
        float2 fn = u2f(num), fd = u2f(den);
        float ssim0 = __fdividef(fn.x, fd.x);
        float ssim1 = __fdividef(fn.y, fd.y);
        ssum[0] += fminf(fmaxf((1.0f - ssim0) * 0.5f, 0.0f), 1.0f);
        ssum[1] += fminf(fmaxf((1.0f - ssim1) * 0.5f, 0.0f), 1.0f);

        // ---- charbonnier L1, packed pair (col0, col1) ----
        float2 cc0 = u2f(cab0), cc1 = u2f(cab1);
        ull dpair = f2u(make_float2(cc0.x - cc0.y, cc1.x - cc1.y));
        float2 dc = u2f(x2fma(dpair, dpair, UEPS2));
        l1sum[0] += fast_sqrt_pos(dc.x);
        l1sum[1] += fast_sqrt_pos(dc.y);
    }

    // ---- finalize cols: photo + LR consistency ----
    float accP = 0.0f, accL = 0.0f;
    #pragma unroll
    for (int k = 0; k < 2; k++) {
        float photo = (ALPHA * (1.0f / 3.0f)) * ssum[k] +
                      ((1.0f - ALPHA) * (1.0f / 3.0f)) * l1sum[k];
        accP += photo * wv[k];
        if (wv[k] != 0.0f) {
            const int g = c0g + k;
            float dl  = dls[k];
            float x   = (float)g - dl;
            float x0f = floorf(x);
            float wx  = x - x0f;
            int   xi  = (int)x0f;
            int x0i = min(max(xi, 0), W - 1);
            int x1i = min(max(xi + 1, 0), W - 1);
            const float* drow = DRb + (size_t)gh * W;
            float drw = (1.0f - wx) * drow[x0i] + wx * drow[x1i];
            float dd = dl - drw;
            accL += fast_sqrt_pos(fmaf(dd, dd, EPS2)) * wv[k];
        }
    }

    // ---- block reduction ----
    #pragma unroll
    for (int o = 16; o > 0; o >>= 1) {
        accP += __shfl_down_sync(0xFFFFFFFFu, accP, o);
        accL += __shfl_down_sync(0xFFFFFFFFu, accL, o);
        accD += __shfl_down_sync(0xFFFFFFFFu, accD, o);
    }
    __shared__ float red[3][8];
    const int lane = threadIdx.x & 31;
    const int wid  = threadIdx.x >> 5;
    if (lane == 0) { red[0][wid] = accP; red[1][wid] = accL; red[2][wid] = accD; }
    __syncthreads();

    __shared__ bool is_last;
    if (threadIdx.x == 0) {
        float p = 0.f, l = 0.f, d = 0.f;
        #pragma unroll
        for (int i = 0; i < 8; i++) { p += red[0][i]; l += red[1][i]; d += red[2][i]; }
        atomicAdd(&g_accP, (double)p);
        atomicAdd(&g_accL, (double)l);
        atomicAdd(&g_accD, (double)d);
        __threadfence();
        unsigned int t = atomicAdd(&g_ticket, 1u);
        is_last = (t == (unsigned int)(nblocks - 1));
    }
    __syncthreads();

    if (is_last && threadIdx.x == 0) {
        __threadfence();
        double tp = atomicAdd(&g_accP, 0.0);
        double tl = atomicAdd(&g_accL, 0.0);
        double td = atomicAdd(&g_accD, 0.0);
        double photo = tp / (td + 1e-6);
        double lr    = tl / (td + 1e-6);
        out[0] = (float)(photo + 0.2 * lr);
        out[1] = (float)photo;
        out[2] = (float)lr;
        out[3] = (float)(td / (double)total_px);
        g_accP = 0.0; g_accL = 0.0; g_accD = 0.0;
        __threadfence();
        g_ticket = 0;
    }
}

extern "C" void kernel_launch(void* const* d_in, const int* in_sizes, int n_in,
                              void* d_out, int out_size) {
    const float* left    = (const float*)d_in[0];
    const float* right   = (const float*)d_in[1];
    const float* d_left  = (const float*)d_in[2];
    const float* d_right = (const float*)d_in[3];
    const float* nonocc  = (const float*)d_in[4];
    float* out = (float*)d_out;

    int B = in_sizes[2] / (IMG_H * IMG_W);   // d_left is [B,1,H,W]

    dim3 grid(IMG_W / TW, IMG_H / TH, B);    // 15 x 64 x B
    int nblocks = grid.x * grid.y * grid.z;

    stereo_loss_kernel<<<grid, NTHR>>>(left, right, d_left, d_right, nonocc,
                                       out, nblocks, B * IMG_H * IMG_W);
}

// round 15
// speedup vs baseline: 1.0861x; 1.0861x over previous
#include <cuda_runtime.h>
#include <cuda_fp16.h>
#include <math.h>

// Fixed shapes: B x 3 x 512 x 960
#define IMG_H 512
#define IMG_W 960
#define NCH 3

#define TW 32
#define TH 16

#define ALPHA 0.85f
#define C1 (0.01f * 0.01f)
#define C2 (0.03f * 0.03f)
#define EPS2 (0.001f * 0.001f)

__device__ double g_accP = 0.0, g_accL = 0.0, g_accD = 0.0;
__device__ unsigned int g_ticket = 0;

__device__ __forceinline__ float fast_sqrt_pos(float x) {
    return x * rsqrtf(x);   // x >= EPS2 > 0
}

typedef unsigned long long ull;
__device__ __forceinline__ ull f2u(float2 v) {
    ull u; asm("mov.b64 %0, {%1, %2};" : "=l"(u) : "f"(v.x), "f"(v.y)); return u;
}
__device__ __forceinline__ float2 u2f(ull u) {
    float2 v; asm("mov.b64 {%0, %1}, %2;" : "=f"(v.x), "=f"(v.y) : "l"(u)); return v;
}
__device__ __forceinline__ ull x2add(ull a, ull b) {
    ull r; asm("add.rn.f32x2 %0, %1, %2;" : "=l"(r) : "l"(a), "l"(b)); return r;
}
__device__ __forceinline__ ull x2mul(ull a, ull b) {
    ull r; asm("mul.rn.f32x2 %0, %1, %2;" : "=l"(r) : "l"(a), "l"(b)); return r;
}
__device__ __forceinline__ ull x2fma(ull a, ull b, ull c) {
    ull r; asm("fma.rn.f32x2 %0, %1, %2, %3;" : "=l"(r) : "l"(a), "l"(b), "l"(c)); return r;
}

__global__ __launch_bounds__(256, 7) void stereo_loss_kernel(
    const float* __restrict__ left,
    const float* __restrict__ right,
    const float* __restrict__ d_left,
    const float* __restrict__ d_right,
    const float* __restrict__ nonocc,
    float* __restrict__ out,
    int nblocks, int total_px)
{
    const int W = IMG_W, H = IMG_H;
    // packed fp16 pair: low = left, high = warped right (4 B/pixel -> half the LDS bytes)
    __shared__ __half2 sAB[NCH][TH + 2][TW + 2];
    __shared__ float   sD[TH + 2][TW + 2];        // d_left stays fp32

    const int w0 = blockIdx.x * TW;
    const int h0 = blockIdx.y * TH;
    const int b  = blockIdx.z;

    const size_t planeHW = (size_t)H * W;
    const float* Lb  = left    + (size_t)b * NCH * planeHW;
    const float* Rb  = right   + (size_t)b * NCH * planeHW;
    const float* Db  = d_left  + (size_t)b * planeHW;
    const float* DRb = d_right + (size_t)b * planeHW;
    const float* Nb  = nonocc  + (size_t)b * planeHW;

    // ---- halo fill (zero outside image: zero-fill + true count == count_include_pad=False) ----
    for (int idx = threadIdx.x; idx < (TH + 2) * (TW + 2); idx += 256) {
        int i = idx / (TW + 2);
        int j = idx - i * (TW + 2);
        int gh = h0 - 1 + i;
        int gw = w0 - 1 + j;
        if (gh >= 0 && gh < H && gw >= 0 && gw < W) {
            float d = Db[(size_t)gh * W + gw];
            sD[i][j] = d;
            float x  = (float)gw - d;
            float x0 = floorf(x);
            float wx = x - x0;
            int   xi = (int)x0;
            int x0i = min(max(xi, 0), W - 1);
            int x1i = min(max(xi + 1, 0), W - 1);
            const float* rrow = Rb + (size_t)gh * W;
            const float* lrow = Lb + (size_t)gh * W;
            #pragma unroll
            for (int c = 0; c < NCH; c++) {
                float v0 = rrow[(size_t)c * planeHW + x0i];
                float v1 = rrow[(size_t)c * planeHW + x1i];
                float bb = (1.0f - wx) * v0 + wx * v1;
                float aa = lrow[(size_t)c * planeHW + gw];
                sAB[c][i][j] = __floats2half2_rn(aa, bb);
            }
        } else {
            sD[i][j] = 0.0f;
            #pragma unroll
            for (int c = 0; c < NCH; c++) sAB[c][i][j] = __floats2half2_rn(0.0f, 0.0f);
        }
    }
    __syncthreads();

    const int tx  = threadIdx.x & 31;       // column within tile
    const int wid = threadIdx.x >> 5;       // warp id: 2-row strip
    const int r0  = wid * 2;                // first output row (0..14)
    const int gw  = w0 + tx;

    // ---- per-row validity / weight; pool-count reciprocal from constants ----
    float wv[2];
    float accD = 0.0f;
    const bool colsIn = (gw > 0) & (gw < W - 1);
    float invk[2];
    #pragma unroll
    for (int k = 0; k < 2; k++) {
        const int gh = h0 + r0 + k;
        float dl = sD[r0 + k + 1][tx + 1];
        float x  = (float)gw - dl;
        float gx = 2.0f * x / (float)(W - 1) - 1.0f;
        float vb = (gx >= -1.0f && gx <= 1.0f) ? 1.0f : 0.0f;
        wv[k] = vb * Nb[(size_t)gh * W + gw];
        accD += wv[k];
        const bool rowsIn = (gh > 0) & (gh < H - 1);
        invk[k] = rowsIn ? (colsIn ? (1.0f / 9.0f) : (1.0f / 6.0f))
                         : (colsIn ? (1.0f / 6.0f) : (1.0f / 4.0f));
    }

    const ull UNEG1 = f2u(make_float2(-1.0f, -1.0f));
    const ull UTWO  = f2u(make_float2(2.0f, 2.0f));
    const ull UC1   = f2u(make_float2(C1, C1));
    const ull UC2   = f2u(make_float2(C2, C2));
    const ull UEPSD = f2u(make_float2(1e-12f, 1e-12f));
    const ull UEPS2 = f2u(make_float2(EPS2, EPS2));
    const ull uinv  = f2u(make_float2(invk[0], invk[1]));

    float ssum[2]  = {0.f, 0.f};
    float l1sum[2] = {0.f, 0.f};

    const __half2 HZERO = __floats2half2_rn(0.0f, 0.0f);

    #pragma unroll
    for (int c = 0; c < NCH; c++) {
        // window moment sums in half2: (sumA,sumB), (sumA2,sumB2), (sumAB,sumAB)
        __half2 v01_0 = HZERO, v23_0 = HZERO, v4_0 = HZERO;   // rows r0-1..r0+1 -> k=0
        __half2 v01_1 = HZERO, v23_1 = HZERO, v4_1 = HZERO;   // rows r0..r0+2   -> k=1
        __half2 cab0 = HZERO, cab1 = HZERO;
        #pragma unroll
        for (int q = 0; q < 4; q++) {
            const int sr = r0 + q;
            __half2 p0 = sAB[c][sr][tx];
            __half2 p1 = sAB[c][sr][tx + 1];
            __half2 p2 = sAB[c][sr][tx + 2];
            __half2 h01 = __hadd2(__hadd2(p0, p1), p2);
            __half2 h23 = __hfma2(p0, p0, __hfma2(p1, p1, __hmul2(p2, p2)));
            __half2 hx  = __hfma2(p0, __lowhigh2highlow(p0),
                          __hfma2(p1, __lowhigh2highlow(p1),
                          __hmul2(p2, __lowhigh2highlow(p2))));
            if (q < 3) {
                v01_0 = __hadd2(v01_0, h01);
                v23_0 = __hadd2(v23_0, h23);
                v4_0  = __hadd2(v4_0, hx);
            }
            if (q >= 1) {
                v01_1 = __hadd2(v01_1, h01);
                v23_1 = __hadd2(v23_1, h23);
                v4_1  = __hadd2(v4_1, hx);
            }
            if (q == 1) cab0 = p1;
            if (q == 2) cab1 = p1;
        }

        // ---- convert window sums to fp32; SSIM consume packed across the two rows ----
        float2 s01_0 = __half22float2(v01_0);
        float2 s01_1 = __half22float2(v01_1);
        float2 s23_0 = __half22float2(v23_0);
        float2 s23_1 = __half22float2(v23_1);
        float2 s4_0  = __half22float2(v4_0);
        float2 s4_1  = __half22float2(v4_1);

        ull sx  = f2u(make_float2(s01_0.x, s01_1.x));
        ull sy  = f2u(make_float2(s01_0.y, s01_1.y));
        ull sxx = f2u(make_float2(s23_0.x, s23_1.x));
        ull syy = f2u(make_float2(s23_0.y, s23_1.y));
        ull sxy = f2u(make_float2(s4_0.x, s4_1.x));

        ull mux  = x2mul(sx, uinv);
        ull muy  = x2mul(sy, uinv);
        ull nmux = x2mul(mux, UNEG1);
        ull nmuy = x2mul(muy, UNEG1);
        ull sigx  = x2fma(nmux, mux, x2mul(sxx, uinv));
        ull sigy  = x2fma(nmuy, muy, x2mul(syy, uinv));
        ull sigxy = x2fma(nmux, muy, x2mul(sxy, uinv));
        ull mm   = x2mul(mux, muy);
        ull num  = x2mul(x2fma(mm, UTWO, UC1), x2fma(sigxy, UTWO, UC2));
        ull den1 = x2fma(mux, mux, x2fma(muy, muy, UC1));
        ull den2 = x2add(x2add(sigx, sigy), UC2);
        ull den  = x2fma(den1, den2, UEPSD);
        float2 fn = u2f(num), fd = u2f(den);
        float ssim0 = __fdividef(fn.x, fd.x);
        float ssim1 = __fdividef(fn.y, fd.y);
        ssum[0] += fminf(fmaxf((1.0f - ssim0) * 0.5f, 0.0f), 1.0f);
        ssum[1] += fminf(fmaxf((1.0f - ssim1) * 0.5f, 0.0f), 1.0f);

        // ---- charbonnier L1, packed pair (row0, row1) ----
        float2 cc0 = __half22float2(cab0);
        float2 cc1 = __half22float2(cab1);
        ull dpair = f2u(make_float2(cc0.x - cc0.y, cc1.x - cc1.y));
        float2 dc = u2f(x2fma(dpair, dpair, UEPS2));
        l1sum[0] += fast_sqrt_pos(dc.x);
        l1sum[1] += fast_sqrt_pos(dc.y);
    }

    // ---- finalize rows: photo + LR consistency (fp32 path, from sD) ----
    float accP = 0.0f, accL = 0.0f;
    #pragma unroll
    for (int k = 0; k < 2; k++) {
        float photo = (ALPHA * (1.0f / 3.0f)) * ssum[k] +
                      ((1.0f - ALPHA) * (1.0f / 3.0f)) * l1sum[k];
        accP += photo * wv[k];
        if (wv[k] != 0.0f) {
            const int gh = h0 + r0 + k;
            float dl  = sD[r0 + k + 1][tx + 1];
            float x   = (float)gw - dl;
            float x0f = floorf(x);
            float wx  = x - x0f;
            int   xi  = (int)x0f;
            int x0i = min(max(xi, 0), W - 1);
            int x1i = min(max(xi + 1, 0), W - 1);
            const float* drow = DRb + (size_t)gh * W;
            float drw = (1.0f - wx) * drow[x0i] + wx * drow[x1i];
            float dd = dl - drw;
            accL += fast_sqrt_pos(fmaf(dd, dd, EPS2)) * wv[k];
        }
    }

    // ---- block reduction ----
    #pragma unroll
    for (int o = 16; o > 0; o >>= 1) {
        accP += __shfl_down_sync(0xFFFFFFFFu, accP, o);
        accL += __shfl_down_sync(0xFFFFFFFFu, accL, o);
        accD += __shfl_down_sync(0xFFFFFFFFu, accD, o);
    }
    __shared__ float red[3][8];
    const int lane = threadIdx.x & 31;
    if (lane == 0) { red[0][wid] = accP; red[1][wid] = accL; red[2][wid] = accD; }
    __syncthreads();

    __shared__ bool is_last;
    if (threadIdx.x == 0) {
        float p = 0.f, l = 0.f, d = 0.f;
        #pragma unroll
        for (int i = 0; i < 8; i++) { p += red[0][i]; l += red[1][i]; d += red[2][i]; }
        atomicAdd(&g_accP, (double)p);
        atomicAdd(&g_accL, (double)l);
        atomicAdd(&g_accD, (double)d);
        __threadfence();
        unsigned int t = atomicAdd(&g_ticket, 1u);
        is_last = (t == (unsigned int)(nblocks - 1));
    }
    __syncthreads();

    if (is_last && threadIdx.x == 0) {
        __threadfence();
        double tp = atomicAdd(&g_accP, 0.0);
        double tl = atomicAdd(&g_accL, 0.0);
        double td = atomicAdd(&g_accD, 0.0);
        double photo = tp / (td + 1e-6);
        double lr    = tl / (td + 1e-6);
        out[0] = (float)(photo + 0.2 * lr);
        out[1] = (float)photo;
        out[2] = (float)lr;
        out[3] = (float)(td / (double)total_px);
        g_accP = 0.0; g_accL = 0.0; g_accD = 0.0;
        __threadfence();
        g_ticket = 0;
    }
}

extern "C" void kernel_launch(void* const* d_in, const int* in_sizes, int n_in,
                              void* d_out, int out_size) {
    const float* left    = (const float*)d_in[0];
    const float* right   = (const float*)d_in[1];
    const float* d_left  = (const float*)d_in[2];
    const float* d_right = (const float*)d_in[3];
    const float* nonocc  = (const float*)d_in[4];
    float* out = (float*)d_out;

    int B = in_sizes[2] / (IMG_H * IMG_W);   // d_left is [B,1,H,W]

    dim3 grid(IMG_W / TW, IMG_H / TH, B);
    int nblocks = grid.x * grid.y * grid.z;

    stereo_loss_kernel<<<grid, 256>>>(left, right, d_left, d_right, nonocc,
                                      out, nblocks, B * IMG_H * IMG_W);
}